// round 7
// baseline (speedup 1.0000x reference)
#include <cuda_runtime.h>
#include <cstdint>

// SLAYER constants
#define ALPHA_F 0.90483741803595952f
#define THETA_F 10.0f

// Problem dims
#define BB   32
#define CIN  156
#define TT   2048
#define HID  512
#define NOUT 20
#define OUTT (TT + CIN)   // 2204

typedef unsigned long long ull;

// ---------------------------------------------------------------------------
// Scratch
// ---------------------------------------------------------------------------
__device__ unsigned char g_s1u8[(size_t)BB * HID * TT];  // branch1 layer1 spikes (u8)
__device__ float         g_a2[(size_t)BB * NOUT * TT];   // branch1 layer2 pre-acts
__device__ float         g_l1[(size_t)BB * CIN * HID];   // branch2 spikes, [b][c][h]
__device__ float         g_l2[(size_t)BB * NOUT * CIN];  // branch2 layer2 pre-acts

// packed fp32x2 FMA: two independent rn-rounded fp32 FMAs (bitwise == scalar fmaf)
__device__ __forceinline__ void ffma2(ull& d, ull a, ull b) {
    asm("fma.rn.f32x2 %0, %1, %2, %0;" : "+l"(d) : "l"(a), "l"(b));
}

// ===========================================================================
// FUSED branch1 layer1 + psp + spike:
//   a1[b,h,t] = sum_c W1[h,c] * X[b,c,t]  (c ascending, single chain)
//   then y[t] = alpha*y[t-1] + a1[t]; spike u8 -> g_s1u8.
// Block = (h0 of 128, b). W tile persistent in smem. 16 t-tiles of 128.
// Packing: acc pairs over h (natural W pairs), X duplicated (x,x) in smem.
// smem: Wsm f32[160][132] @0 (84480) | Xd ull[16][132] @84480 (16896)
//       Ct f32[128][129] @101376 (66048) | Cu8 u8[128][132] @167424 (16896)
// ===========================================================================
#define B1_SMEM (84480 + 16896 + 66048 + 16896)

__global__ __launch_bounds__(256) void k_b1l1_psp(const float* __restrict__ X,
                                                  const float* __restrict__ W1) {
    extern __shared__ char smraw[];
    float* Wsm = (float*)smraw;
    ull*   Xd  = (ull*)(smraw + 84480);
    float* Ct  = (float*)(smraw + 101376);
    unsigned char* Cu8 = (unsigned char*)(smraw + 167424);

    const int b  = blockIdx.y;
    const int h0 = blockIdx.x * 128;
    const int tid = threadIdx.x;
    const int tx = tid & 15, ty = tid >> 4;
    const float* Xb = X + (size_t)b * CIN * TT;

    // Persistent W tile: Wsm[c][h], zero pad c>=156
    for (int idx = tid; idx < 160 * 128; idx += 256) {
        int h = idx / 160;
        int c = idx - h * 160;
        Wsm[c * 132 + h] = (c < CIN) ? W1[(h0 + h) * CIN + c] : 0.0f;
    }

    float ycar = 0.0f;   // psp carry for row h=tid (threads 0..127)

    for (int t0 = 0; t0 < TT; t0 += 128) {
        ull acc[4][8];
#pragma unroll
        for (int i = 0; i < 4; i++)
#pragma unroll
            for (int j = 0; j < 8; j++) acc[i][j] = 0ULL;

        // prefetch slab 0 (16 c-rows x 128 t)
        float4 vx[2];
#pragma unroll
        for (int i = 0; i < 2; i++) {
            int idx = tid + 256 * i;
            int k = idx >> 5, tq = idx & 31;
            vx[i] = (k < CIN) ? *(const float4*)(Xb + (size_t)k * TT + t0 + tq * 4)
                              : make_float4(0.f, 0.f, 0.f, 0.f);
        }

        for (int k0 = 0; k0 < 160; k0 += 16) {
            __syncthreads();   // Xd free (also covers Wsm fill / prev-tile epilogue)
#pragma unroll
            for (int i = 0; i < 2; i++) {
                int idx = tid + 256 * i;
                int k = idx >> 5, tq = idx & 31;
                float2* dst = (float2*)(Xd + k * 132 + tq * 4);
                dst[0] = make_float2(vx[i].x, vx[i].x);
                dst[1] = make_float2(vx[i].y, vx[i].y);
                dst[2] = make_float2(vx[i].z, vx[i].z);
                dst[3] = make_float2(vx[i].w, vx[i].w);
            }
            __syncthreads();
            if (k0 + 16 < 160) {
#pragma unroll
                for (int i = 0; i < 2; i++) {
                    int idx = tid + 256 * i;
                    int k = idx >> 5, tq = idx & 31;
                    int c = k0 + 16 + k;
                    vx[i] = (c < CIN)
                          ? *(const float4*)(Xb + (size_t)c * TT + t0 + tq * 4)
                          : make_float4(0.f, 0.f, 0.f, 0.f);
                }
            }
#pragma unroll
            for (int k = 0; k < 16; k++) {
                const float* wr = Wsm + (k0 + k) * 132 + ty * 8;
                ulonglong2 a01 = *(const ulonglong2*)(wr);
                ulonglong2 a23 = *(const ulonglong2*)(wr + 4);
                ull a[4] = {a01.x, a01.y, a23.x, a23.y};
                const ull* br = Xd + k * 132 + tx * 8;
                ulonglong2 b01 = *(const ulonglong2*)(br);
                ulonglong2 b23 = *(const ulonglong2*)(br + 2);
                ulonglong2 b45 = *(const ulonglong2*)(br + 4);
                ulonglong2 b67 = *(const ulonglong2*)(br + 6);
                ull bx[8] = {b01.x, b01.y, b23.x, b23.y, b45.x, b45.y, b67.x, b67.y};
#pragma unroll
                for (int i = 0; i < 4; i++)
#pragma unroll
                    for (int j = 0; j < 8; j++)
                        ffma2(acc[i][j], a[i], bx[j]);
            }
        }

        // epilogue: acc pairs (h=2i, h=2i+1) -> Ct[h][t]
#pragma unroll
        for (int i = 0; i < 4; i++)
#pragma unroll
            for (int j = 0; j < 8; j++) {
                float2 f = *(float2*)&acc[i][j];
                int hl = ty * 8 + 2 * i, t = tx * 8 + j;
                Ct[hl * 129 + t]       = f.x;
                Ct[(hl + 1) * 129 + t] = f.y;
            }
        __syncthreads();

        // fused psp scan + spike (threads 0..127, carry in reg)
        if (tid < 128) {
            float y = ycar;
            const float* row = Ct + tid * 129;
            unsigned char* orow = Cu8 + tid * 132;
#pragma unroll 8
            for (int t = 0; t < 128; t++) {
                y = fmaf(ALPHA_F, y, row[t]);
                orow[t] = (y >= THETA_F) ? (unsigned char)1 : (unsigned char)0;
            }
            ycar = y;
        }
        __syncthreads();

        // coalesced u8 copy-out
        unsigned char* dstbase = g_s1u8 + ((size_t)b * HID + h0) * TT + t0;
#pragma unroll
        for (int i2 = 0; i2 < 16; i2++) {
            int w = tid + 256 * i2;          // 0..4095
            int row = w >> 5, q = w & 31;
            unsigned v = *(const unsigned*)(Cu8 + row * 132 + q * 4);
            *(unsigned*)(dstbase + (size_t)row * TT + q * 4) = v;
        }
        // next iteration's first __syncthreads protects Ct/Cu8 reuse
    }
}

// ===========================================================================
// FUSED branch2 layer1 + psp + spike:
//   l1a[b,h,c] = sum_t Wl1[h,t] * X[b,perm[c],t]  (t ascending chain)
//   then scan over c, spikes (float) -> g_l1[b][c][h].
// Block = (h0 of 128, b); all 156 c (pad 160) in-block. K = 2048, slabs of 16.
// smem: Ws f32[16][132] @0 (8448) | Bd ull[16][164] @8448 (20992)
//       Ct f32[128][161] @29440 (82432) | prow i32[160] @111872
// ===========================================================================
#define B2_SMEM (8448 + 20992 + 82432 + 640)

__global__ __launch_bounds__(256) void k_b2l1_psp(const float* __restrict__ X,
                                                  const float* __restrict__ Wl1,
                                                  const int* __restrict__ perm) {
    extern __shared__ char smraw[];
    float* Ws  = (float*)smraw;
    ull*   Bd  = (ull*)(smraw + 8448);
    float* Ct  = (float*)(smraw + 29440);
    int*   prow = (int*)(smraw + 111872);

    const int b  = blockIdx.y;
    const int h0 = blockIdx.x * 128;
    const int tid = threadIdx.x;
    const int tx = tid & 15, ty = tid >> 4;
    const float* Xb = X + (size_t)b * CIN * TT;

    if (tid < 160) prow[tid] = (tid < CIN) ? perm[tid] : 0;
    __syncthreads();

    ull acc[4][10];
#pragma unroll
    for (int i = 0; i < 4; i++)
#pragma unroll
        for (int j = 0; j < 10; j++) acc[i][j] = 0ULL;

    // prefetch slab 0
    float4 vw[2], vb[3];
#pragma unroll
    for (int i = 0; i < 2; i++) {
        int idx = tid + 256 * i;           // 0..511
        int h = idx >> 2, kq = idx & 3;
        vw[i] = *(const float4*)(Wl1 + (size_t)(h0 + h) * TT + kq * 4);
    }
#pragma unroll
    for (int i = 0; i < 3; i++) {
        int idx = tid + 256 * i;           // 0..767, valid < 624
        if (idx < CIN * 4) {
            int c = idx >> 2, kq = idx & 3;
            vb[i] = *(const float4*)(Xb + (size_t)prow[c] * TT + kq * 4);
        }
    }

    for (int k0 = 0; k0 < TT; k0 += 16) {
        __syncthreads();
        // store prefetched slab
#pragma unroll
        for (int i = 0; i < 2; i++) {
            int idx = tid + 256 * i;
            int h = idx >> 2, kq = idx & 3;
            Ws[(kq * 4 + 0) * 132 + h] = vw[i].x;
            Ws[(kq * 4 + 1) * 132 + h] = vw[i].y;
            Ws[(kq * 4 + 2) * 132 + h] = vw[i].z;
            Ws[(kq * 4 + 3) * 132 + h] = vw[i].w;
        }
#pragma unroll
        for (int i = 0; i < 3; i++) {
            int idx = tid + 256 * i;
            if (idx < CIN * 4) {
                int c = idx >> 2, kq = idx & 3;
                ((float2*)Bd)[(kq * 4 + 0) * 164 + c] = make_float2(vb[i].x, vb[i].x);
                ((float2*)Bd)[(kq * 4 + 1) * 164 + c] = make_float2(vb[i].y, vb[i].y);
                ((float2*)Bd)[(kq * 4 + 2) * 164 + c] = make_float2(vb[i].z, vb[i].z);
                ((float2*)Bd)[(kq * 4 + 3) * 164 + c] = make_float2(vb[i].w, vb[i].w);
            }
        }
        __syncthreads();
        if (k0 + 16 < TT) {
            int kn = k0 + 16;
#pragma unroll
            for (int i = 0; i < 2; i++) {
                int idx = tid + 256 * i;
                int h = idx >> 2, kq = idx & 3;
                vw[i] = *(const float4*)(Wl1 + (size_t)(h0 + h) * TT + kn + kq * 4);
            }
#pragma unroll
            for (int i = 0; i < 3; i++) {
                int idx = tid + 256 * i;
                if (idx < CIN * 4) {
                    int c = idx >> 2, kq = idx & 3;
                    vb[i] = *(const float4*)(Xb + (size_t)prow[c] * TT + kn + kq * 4);
                }
            }
        }
#pragma unroll
        for (int k = 0; k < 16; k++) {
            const float* wr = Ws + k * 132 + ty * 8;
            ulonglong2 a01 = *(const ulonglong2*)(wr);
            ulonglong2 a23 = *(const ulonglong2*)(wr + 4);
            ull a[4] = {a01.x, a01.y, a23.x, a23.y};
            const ull* br = Bd + k * 164 + tx * 10;
            ulonglong2 b01 = *(const ulonglong2*)(br);
            ulonglong2 b23 = *(const ulonglong2*)(br + 2);
            ulonglong2 b45 = *(const ulonglong2*)(br + 4);
            ulonglong2 b67 = *(const ulonglong2*)(br + 6);
            ulonglong2 b89 = *(const ulonglong2*)(br + 8);
            ull bx[10] = {b01.x, b01.y, b23.x, b23.y, b45.x,
                          b45.y, b67.x, b67.y, b89.x, b89.y};
#pragma unroll
            for (int i = 0; i < 4; i++)
#pragma unroll
                for (int j = 0; j < 10; j++)
                    ffma2(acc[i][j], a[i], bx[j]);
        }
    }

    // epilogue: pairs (h=2i,h=2i+1) at c = tx*10+j -> Ct[h][c]
    __syncthreads();
#pragma unroll
    for (int i = 0; i < 4; i++)
#pragma unroll
        for (int j = 0; j < 10; j++) {
            float2 f = *(float2*)&acc[i][j];
            int hl = ty * 8 + 2 * i, c = tx * 10 + j;
            Ct[hl * 161 + c]       = f.x;
            Ct[(hl + 1) * 161 + c] = f.y;
        }
    __syncthreads();

    // fused psp scan over c + spike (float), in-place in Ct
    if (tid < 128) {
        float y = 0.0f;
        float* row = Ct + tid * 161;
#pragma unroll 4
        for (int c = 0; c < CIN; c++) {
            y = fmaf(ALPHA_F, y, row[c]);
            row[c] = (y >= THETA_F) ? 1.0f : 0.0f;
        }
    }
    __syncthreads();

    // coalesced store to g_l1[b][c][h0..h0+127]
    float* dstb = g_l1 + (size_t)b * CIN * HID + h0;
    for (int idx = tid; idx < CIN * 128; idx += 256) {
        int c = idx >> 7, hl = idx & 127;
        dstb[(size_t)c * HID + hl] = Ct[hl * 161 + c];
    }
}

// ---------------------------------------------------------------------------
// Branch1 layer2: a2[b,o,t] = sum_h W2[o,h] * s1u8[b,h,t]
// ---------------------------------------------------------------------------
__global__ __launch_bounds__(128) void k_gemm_b1l2(const float* __restrict__ W2) {
    __shared__ ull Wsd[32 * 36];
    __shared__ float Ssf[32 * 72];

    const int b  = blockIdx.y;
    const int t0 = blockIdx.x * 64;
    const int tid = threadIdx.x;
    const int tx = tid & 15;
    const int ty = tid >> 4;
    const unsigned char* Sb = g_s1u8 + (size_t)b * HID * TT;

    ull acc[4][2];
#pragma unroll
    for (int i = 0; i < 4; i++) { acc[i][0] = 0ULL; acc[i][1] = 0ULL; }

    for (int k0 = 0; k0 < HID; k0 += 32) {
#pragma unroll
        for (int i = 0; i < 8; i++) {
            int idx = tid + 128 * i;
            int o = idx >> 5, k = idx & 31;
            float v = (o < NOUT) ? W2[o * HID + k0 + k] : 0.0f;
            ((float2*)Wsd)[k * 36 + o] = make_float2(v, v);
        }
#pragma unroll
        for (int i = 0; i < 4; i++) {
            int idx = tid + 128 * i;
            int k = idx >> 4, tq = idx & 15;
            uchar4 u = *(const uchar4*)(Sb + (size_t)(k0 + k) * TT + t0 + tq * 4);
            *(float4*)&Ssf[k * 72 + tq * 4] =
                make_float4((float)u.x, (float)u.y, (float)u.z, (float)u.w);
        }
        __syncthreads();
#pragma unroll
        for (int k = 0; k < 32; k++) {
            ull a[4], bq[2];
            ulonglong2 aa = *(const ulonglong2*)(Wsd + k * 36 + ty * 4);
            a[0] = aa.x; a[1] = aa.y;
            ulonglong2 aa2 = *(const ulonglong2*)(Wsd + k * 36 + ty * 4 + 2);
            a[2] = aa2.x; a[3] = aa2.y;
            ulonglong2 bb = *(const ulonglong2*)((const ull*)(Ssf + k * 72 + tx * 4));
            bq[0] = bb.x; bq[1] = bb.y;
#pragma unroll
            for (int i = 0; i < 4; i++) {
                ffma2(acc[i][0], a[i], bq[0]);
                ffma2(acc[i][1], a[i], bq[1]);
            }
        }
        __syncthreads();
    }

#pragma unroll
    for (int i = 0; i < 4; i++) {
        int o = ty * 4 + i;
        if (o < NOUT) {
            float* op = g_a2 + ((size_t)b * NOUT + o) * TT + t0 + tx * 4;
            *(ull*)(op)     = acc[i][0];
            *(ull*)(op + 2) = acc[i][1];
        }
    }
}

// ---------------------------------------------------------------------------
// Warp-per-row output scans (unchanged)
// ---------------------------------------------------------------------------
__device__ __forceinline__ void scan_rows(const float* __restrict__ in,
                                          float* __restrict__ out,
                                          int len, int out_off) {
    __shared__ float4 buf[8][32];
    const int w = threadIdx.x >> 5, lane = threadIdx.x & 31;
    const int row = blockIdx.x * 8 + w;
    const float* ip = in + (size_t)row * len;
    float* op = out + (size_t)row * OUTT + out_off;
    const int nch = (len + 127) / 128;

    float y = 0.0f;
    int idx = lane * 4;
    float4 v = make_float4(0.f, 0.f, 0.f, 0.f);
    if (idx < len) v = *(const float4*)(ip + idx);

    for (int ch = 0; ch < nch; ch++) {
        buf[w][lane] = v;
        __syncwarp();
        int nidx = (ch + 1) * 128 + lane * 4;
        if (nidx < len) v = *(const float4*)(ip + nidx);
        if (lane == 0) {
            int n4 = (len - ch * 128) >> 2; if (n4 > 32) n4 = 32;
            for (int i = 0; i < n4; i++) {
                float4 u = buf[w][i]; float4 s;
                y = fmaf(ALPHA_F, y, u.x); s.x = (y >= THETA_F) ? 1.0f : 0.0f;
                y = fmaf(ALPHA_F, y, u.y); s.y = (y >= THETA_F) ? 1.0f : 0.0f;
                y = fmaf(ALPHA_F, y, u.z); s.z = (y >= THETA_F) ? 1.0f : 0.0f;
                y = fmaf(ALPHA_F, y, u.w); s.w = (y >= THETA_F) ? 1.0f : 0.0f;
                buf[w][i] = s;
            }
        }
        __syncwarp();
        int oi = ch * 128 + lane * 4;
        if (oi < len) *(float4*)(op + oi) = buf[w][lane];
        __syncwarp();
    }
}

__global__ __launch_bounds__(256) void k_scan_a2(float* __restrict__ out) {
    scan_rows(g_a2, out, TT, 0);
}
__global__ __launch_bounds__(256) void k_scan_l2(float* __restrict__ out) {
    scan_rows(g_l2, out, CIN, TT);
}

// ---------------------------------------------------------------------------
// Branch2 layer2: l2[b,o,c] = sum_h Wl2[o,h] * l1[b,c,h]
// ---------------------------------------------------------------------------
__global__ __launch_bounds__(160) void k_gemm_b2l2(const float* __restrict__ Wl2) {
    __shared__ float Ws[4 * HID];
    const int og = blockIdx.x;
    const int b  = blockIdx.y;
    const int tid = threadIdx.x;

    for (int idx = tid; idx < 4 * HID; idx += 160)
        Ws[idx] = Wl2[(og * 4 + (idx >> 9)) * HID + (idx & (HID - 1))];
    __syncthreads();

    const int c = tid;
    if (c >= CIN) return;
    const float* Lb = g_l1 + ((size_t)b * CIN + c) * HID;
    float acc[4] = {0.f, 0.f, 0.f, 0.f};

#pragma unroll 4
    for (int h = 0; h < HID; h += 4) {
        float4 xv = *(const float4*)(Lb + h);
#pragma unroll
        for (int o = 0; o < 4; o++) {
            const float4 w = *(const float4*)&Ws[o * HID + h];
            acc[o] = fmaf(w.x, xv.x, acc[o]);
            acc[o] = fmaf(w.y, xv.y, acc[o]);
            acc[o] = fmaf(w.z, xv.z, acc[o]);
            acc[o] = fmaf(w.w, xv.w, acc[o]);
        }
    }
#pragma unroll
    for (int o = 0; o < 4; o++)
        g_l2[((size_t)b * NOUT + og * 4 + o) * CIN + c] = acc[o];
}

// ---------------------------------------------------------------------------
// Launch
// ---------------------------------------------------------------------------
extern "C" void kernel_launch(void* const* d_in, const int* in_sizes, int n_in,
                              void* d_out, int out_size) {
    (void)in_sizes; (void)n_in; (void)out_size;
    const float* X    = (const float*)d_in[0];
    const float* W1   = (const float*)d_in[1];
    const float* W2   = (const float*)d_in[2];
    const float* Wl1  = (const float*)d_in[3];
    const float* Wl2  = (const float*)d_in[4];
    const int*   perm = (const int*)d_in[5];
    float* out = (float*)d_out;

    cudaFuncSetAttribute(k_b1l1_psp, cudaFuncAttributeMaxDynamicSharedMemorySize, B1_SMEM);
    cudaFuncSetAttribute(k_b2l1_psp, cudaFuncAttributeMaxDynamicSharedMemorySize, B2_SMEM);

    // Branch 1 (fused GEMM+psp, then layer2, then output scan)
    k_b1l1_psp<<<dim3(HID / 128, BB), 256, B1_SMEM>>>(X, W1);
    k_gemm_b1l2<<<dim3(TT / 64, BB), 128>>>(W2);
    k_scan_a2<<<BB * NOUT / 8, 256>>>(out);

    // Branch 2
    k_b2l1_psp<<<dim3(HID / 128, BB), 256, B2_SMEM>>>(X, Wl1, perm);
    k_gemm_b2l2<<<dim3(5, BB), 160>>>(Wl2);
    k_scan_l2<<<BB * NOUT / 8, 256>>>(out);
}

// round 8
// speedup vs baseline: 1.4933x; 1.4933x over previous
#include <cuda_runtime.h>
#include <cstdint>

// SLAYER constants
#define ALPHA_F 0.90483741803595952f
#define THETA_F 10.0f

// Problem dims
#define BB   32
#define CIN  156
#define TT   2048
#define HID  512
#define NOUT 20
#define OUTT (TT + CIN)   // 2204

typedef unsigned long long ull;

// ---------------------------------------------------------------------------
// Scratch
// ---------------------------------------------------------------------------
__device__ unsigned char g_s1u8[(size_t)BB * HID * TT];  // branch1 layer1 spikes (u8)
__device__ float         g_a2[(size_t)BB * NOUT * TT];   // branch1 layer2 pre-acts
__device__ float         g_l1[(size_t)BB * CIN * HID];   // branch2 spikes, [b][c][h]
__device__ float         g_l2[(size_t)BB * NOUT * CIN];  // branch2 layer2 pre-acts

// packed fp32x2 FMA: two independent rn-rounded fp32 FMAs (bitwise == scalar fmaf)
__device__ __forceinline__ void ffma2(ull& d, ull a, ull b) {
    asm("fma.rn.f32x2 %0, %1, %2, %0;" : "+l"(d) : "l"(a), "l"(b));
}
__device__ __forceinline__ ull dup2(float v) {
    float2 f = make_float2(v, v);
    return *(ull*)&f;
}

// ===========================================================================
// FUSED branch1 layer1 + psp + spike.
//   a1[b,h,t] = sum_c W1[h,c]*X[b,c,t] (c ascending 0..159, zero-padded)
//   y[t] = alpha*y[t-1] + a1[t]; spike -> u8 g_s1u8.
// Block (h0=128h, b), 512 threads, 16 t-tiles of 128, BK=16 double-buffered.
// A = W1 duplicated pairs (broadcast LDS.64), B = X natural pairs (1 LDS.128).
// Thread: tx=tid&31 -> 4 t (2 pairs), ty=tid>>5 -> 8 h.  acc[8][2].
// smem: Asd ull[2][16*133] @0 | Bsf f32[2][16*132] @34048
//       Ct f32[128][132] @50944 | Cu8 u8[128][132] @118528   total 135424
// ===========================================================================
#define B1_SMEM 135424

__global__ __launch_bounds__(512) void k_b1l1_psp(const float* __restrict__ X,
                                                  const float* __restrict__ W1) {
    extern __shared__ char sm[];
    ull*   Asd = (ull*)sm;                         // [2][16*133]
    float* Bsf = (float*)(sm + 34048);             // [2][16*132]
    float* Ct  = (float*)(sm + 50944);             // [128][132]
    unsigned char* Cu8 = (unsigned char*)(sm + 118528);

    const int b  = blockIdx.y;
    const int h0 = blockIdx.x * 128;
    const int tid = threadIdx.x;
    const int tx = tid & 31, ty = tid >> 5;
    const int ha = tid >> 2, cq = tid & 3;         // A-fill map
    const int kb = tid >> 5, t4 = tid & 31;        // B-fill map (== ty, tx)
    const float* Xb = X + (size_t)b * CIN * TT;
    const float* Wr = W1 + (size_t)(h0 + ha) * CIN;

    float ycar = 0.0f;                             // psp carry (threads 0..127)

    for (int t0 = 0; t0 < TT; t0 += 128) {
        ull acc[8][2];
#pragma unroll
        for (int i = 0; i < 8; i++) { acc[i][0] = 0ULL; acc[i][1] = 0ULL; }

        // ---- prologue: load + store slab 0 ----
        float4 va, vb;
        {
            int c = cq * 4;
            va = (c < CIN) ? *(const float4*)(Wr + c) : make_float4(0.f,0.f,0.f,0.f);
            vb = (kb < CIN) ? *(const float4*)(Xb + (size_t)kb * TT + t0 + t4 * 4)
                            : make_float4(0.f,0.f,0.f,0.f);
        }
        {
            ull* Ad = Asd;  float* Bd = Bsf;
            Ad[(cq*4+0)*133 + ha] = dup2(va.x);
            Ad[(cq*4+1)*133 + ha] = dup2(va.y);
            Ad[(cq*4+2)*133 + ha] = dup2(va.z);
            Ad[(cq*4+3)*133 + ha] = dup2(va.w);
            *(float4*)(Bd + kb*132 + t4*4) = vb;
        }
        __syncthreads();

        for (int s = 0; s < 10; s++) {
            const int buf = s & 1;
            const bool more = (s + 1 < 10);
            if (more) {
                int k0 = (s + 1) * 16;
                int c  = k0 + cq * 4;
                va = (c < CIN) ? *(const float4*)(Wr + c) : make_float4(0.f,0.f,0.f,0.f);
                int ck = k0 + kb;
                vb = (ck < CIN) ? *(const float4*)(Xb + (size_t)ck * TT + t0 + t4 * 4)
                                : make_float4(0.f,0.f,0.f,0.f);
            }
            const ull*   Ab = Asd + buf * (16*133);
            const float* Bb = Bsf + buf * (16*132);
#pragma unroll
            for (int k = 0; k < 16; k++) {
                const ull* Ar = Ab + k * 133 + ty * 8;
                ull a0 = Ar[0], a1 = Ar[1], a2 = Ar[2], a3 = Ar[3];
                ull a4 = Ar[4], a5 = Ar[5], a6 = Ar[6], a7 = Ar[7];
                ulonglong2 bb = *((const ulonglong2*)(Bb + k * 132) + tx);
                ffma2(acc[0][0], a0, bb.x); ffma2(acc[0][1], a0, bb.y);
                ffma2(acc[1][0], a1, bb.x); ffma2(acc[1][1], a1, bb.y);
                ffma2(acc[2][0], a2, bb.x); ffma2(acc[2][1], a2, bb.y);
                ffma2(acc[3][0], a3, bb.x); ffma2(acc[3][1], a3, bb.y);
                ffma2(acc[4][0], a4, bb.x); ffma2(acc[4][1], a4, bb.y);
                ffma2(acc[5][0], a5, bb.x); ffma2(acc[5][1], a5, bb.y);
                ffma2(acc[6][0], a6, bb.x); ffma2(acc[6][1], a6, bb.y);
                ffma2(acc[7][0], a7, bb.x); ffma2(acc[7][1], a7, bb.y);
            }
            if (more) {
                ull* Ad = Asd + (buf ^ 1) * (16*133);
                float* Bd = Bsf + (buf ^ 1) * (16*132);
                Ad[(cq*4+0)*133 + ha] = dup2(va.x);
                Ad[(cq*4+1)*133 + ha] = dup2(va.y);
                Ad[(cq*4+2)*133 + ha] = dup2(va.z);
                Ad[(cq*4+3)*133 + ha] = dup2(va.w);
                *(float4*)(Bd + kb*132 + t4*4) = vb;
                __syncthreads();
            }
        }

        // ---- epilogue: acc -> Ct[h][t] (pairs are over t: natural) ----
#pragma unroll
        for (int i = 0; i < 8; i++) {
#pragma unroll
            for (int j = 0; j < 2; j++) {
                float2 f = *(float2*)&acc[i][j];
                *(float2*)(Ct + (ty*8 + i)*132 + tx*4 + 2*j) = f;
            }
        }
        __syncthreads();

        // ---- fused psp scan + spike ----
        if (tid < 128) {
            float y = ycar;
            const float* row = Ct + tid * 132;
            unsigned* orow = (unsigned*)(Cu8 + tid * 132);
#pragma unroll 4
            for (int q = 0; q < 32; q++) {
                float4 v = *(const float4*)(row + q * 4);
                unsigned pk;
                y = fmaf(ALPHA_F, y, v.x); pk  = (y >= THETA_F) ? 1u : 0u;
                y = fmaf(ALPHA_F, y, v.y); pk |= (y >= THETA_F) ? (1u<<8) : 0u;
                y = fmaf(ALPHA_F, y, v.z); pk |= (y >= THETA_F) ? (1u<<16) : 0u;
                y = fmaf(ALPHA_F, y, v.w); pk |= (y >= THETA_F) ? (1u<<24) : 0u;
                orow[q] = pk;
            }
            ycar = y;
        }
        __syncthreads();

        // ---- coalesced u8 copy-out ----
        unsigned char* dstb = g_s1u8 + ((size_t)b * HID + h0) * TT + t0;
#pragma unroll
        for (int it = 0; it < 8; it++) {
            int idx = tid + 512 * it;          // 0..4095
            int row = idx >> 5, q = idx & 31;
            unsigned v = *(const unsigned*)(Cu8 + row * 132 + q * 4);
            *(unsigned*)(dstb + (size_t)row * TT + q * 4) = v;
        }
        __syncthreads();   // Ct/Cu8/buffers free for next tile
    }
}

// ===========================================================================
// FUSED branch2 layer1 + psp + spike.
//   l1a[b,h,c] = sum_t Wl1[h,t]*X[b,perm[c],t] (t ascending 0..2047)
//   scan over c; spikes (f32) -> g_l1[b][c][h].
// Block (h0=128h, b), 512 threads, whole c (156) per block, BK=16 dbl-buffered.
// A = Wl1 dup pairs (broadcast), B = X natural pairs over c (5 LDS.64).
// Thread: tx=tid&15 -> 10 c (5 pairs), ty=tid>>4 -> 4 h.  acc[4][5].
// smem: Asd ull[2][16*133] @0 | Bsf f32[2][16*170] @34048
//       Ct f32[128][170] @55808 | prow @142848   total 143488
// ===========================================================================
#define B2_SMEM 143488

__global__ __launch_bounds__(512) void k_b2l1_psp(const float* __restrict__ X,
                                                  const float* __restrict__ Wl1,
                                                  const int* __restrict__ perm) {
    extern __shared__ char sm[];
    ull*   Asd = (ull*)sm;                        // [2][16*133]
    float* Bsf = (float*)(sm + 34048);            // [2][16*170]
    float* Ct  = (float*)(sm + 55808);            // [128][170]
    int*   prow = (int*)(sm + 142848);

    const int b  = blockIdx.y;
    const int h0 = blockIdx.x * 128;
    const int tid = threadIdx.x;
    const int tx = tid & 15, ty = tid >> 4;
    const int ha = tid >> 2, kqa = tid & 3;       // A-fill map
    const int cb = tid >> 2, kqb = tid & 3;       // B-fill map (it 0); it 1 masked
    const float* Xb = X + (size_t)b * CIN * TT;
    const float* Wr = Wl1 + (size_t)(h0 + ha) * TT;

    if (tid < 160) prow[tid] = (tid < CIN) ? perm[tid] : 0;
    __syncthreads();

    ull acc[4][5];
#pragma unroll
    for (int i = 0; i < 4; i++)
#pragma unroll
        for (int q = 0; q < 5; q++) acc[i][q] = 0ULL;

    // B fill second chunk: idx = tid+512 in [512,624)
    const int cb2 = (tid + 512) >> 2;             // valid iff tid < 112
    const bool b2v = (tid < 112);

    // ---- prologue slab 0 ----
    float4 va, vb0, vb1;
    va  = *(const float4*)(Wr + kqa * 4);
    vb0 = *(const float4*)(Xb + (size_t)prow[cb] * TT + kqb * 4);
    vb1 = b2v ? *(const float4*)(Xb + (size_t)prow[cb2] * TT + kqb * 4)
              : make_float4(0.f,0.f,0.f,0.f);
    {
        ull* Ad = Asd;  float* Bd = Bsf;
        Ad[(kqa*4+0)*133 + ha] = dup2(va.x);
        Ad[(kqa*4+1)*133 + ha] = dup2(va.y);
        Ad[(kqa*4+2)*133 + ha] = dup2(va.z);
        Ad[(kqa*4+3)*133 + ha] = dup2(va.w);
        Bd[(kqb*4+0)*170 + cb] = vb0.x;
        Bd[(kqb*4+1)*170 + cb] = vb0.y;
        Bd[(kqb*4+2)*170 + cb] = vb0.z;
        Bd[(kqb*4+3)*170 + cb] = vb0.w;
        if (b2v) {
            Bd[(kqb*4+0)*170 + cb2] = vb1.x;
            Bd[(kqb*4+1)*170 + cb2] = vb1.y;
            Bd[(kqb*4+2)*170 + cb2] = vb1.z;
            Bd[(kqb*4+3)*170 + cb2] = vb1.w;
        }
    }
    __syncthreads();

    for (int s = 0; s < TT / 16; s++) {
        const int buf = s & 1;
        const bool more = (s + 1 < TT / 16);
        if (more) {
            int k0 = (s + 1) * 16;
            va  = *(const float4*)(Wr + k0 + kqa * 4);
            vb0 = *(const float4*)(Xb + (size_t)prow[cb] * TT + k0 + kqb * 4);
            if (b2v)
                vb1 = *(const float4*)(Xb + (size_t)prow[cb2] * TT + k0 + kqb * 4);
        }
        const ull*   Ab = Asd + buf * (16*133);
        const float* Bb = Bsf + buf * (16*170);
#pragma unroll
        for (int k = 0; k < 16; k++) {
            const ull* Ar = Ab + k * 133 + ty * 4;
            ull a0 = Ar[0], a1 = Ar[1], a2 = Ar[2], a3 = Ar[3];
            const ull* Br = (const ull*)(Bb + k * 170) + tx * 5;
            ull b0 = Br[0], b1 = Br[1], b2 = Br[2], b3 = Br[3], b4 = Br[4];
#pragma unroll
            for (int q = 0; q < 5; q++) {
                ull bv = (q==0)?b0:(q==1)?b1:(q==2)?b2:(q==3)?b3:b4;
                ffma2(acc[0][q], a0, bv);
                ffma2(acc[1][q], a1, bv);
                ffma2(acc[2][q], a2, bv);
                ffma2(acc[3][q], a3, bv);
            }
        }
        if (more) {
            ull* Ad = Asd + (buf ^ 1) * (16*133);
            float* Bd = Bsf + (buf ^ 1) * (16*170);
            Ad[(kqa*4+0)*133 + ha] = dup2(va.x);
            Ad[(kqa*4+1)*133 + ha] = dup2(va.y);
            Ad[(kqa*4+2)*133 + ha] = dup2(va.z);
            Ad[(kqa*4+3)*133 + ha] = dup2(va.w);
            Bd[(kqb*4+0)*170 + cb] = vb0.x;
            Bd[(kqb*4+1)*170 + cb] = vb0.y;
            Bd[(kqb*4+2)*170 + cb] = vb0.z;
            Bd[(kqb*4+3)*170 + cb] = vb0.w;
            if (b2v) {
                Bd[(kqb*4+0)*170 + cb2] = vb1.x;
                Bd[(kqb*4+1)*170 + cb2] = vb1.y;
                Bd[(kqb*4+2)*170 + cb2] = vb1.z;
                Bd[(kqb*4+3)*170 + cb2] = vb1.w;
            }
            __syncthreads();
        }
    }

    // ---- epilogue: acc (pairs over c, natural) -> Ct[h][c] ----
    __syncthreads();
#pragma unroll
    for (int i = 0; i < 4; i++)
#pragma unroll
        for (int q = 0; q < 5; q++) {
            float2 f = *(float2*)&acc[i][q];
            *(float2*)(Ct + (ty*4 + i)*170 + tx*10 + 2*q) = f;
        }
    __syncthreads();

    // ---- fused psp scan over c + spike (in-place float) ----
    if (tid < 128) {
        float y = 0.0f;
        float* row = Ct + tid * 170;
#pragma unroll 4
        for (int c = 0; c < CIN; c++) {
            y = fmaf(ALPHA_F, y, row[c]);
            row[c] = (y >= THETA_F) ? 1.0f : 0.0f;
        }
    }
    __syncthreads();

    // ---- coalesced store to g_l1[b][c][h0..h0+127] ----
    float* dstb = g_l1 + (size_t)b * CIN * HID + h0;
    for (int idx = tid; idx < CIN * 128; idx += 512) {
        int c = idx >> 7, hh = idx & 127;
        dstb[(size_t)c * HID + hh] = Ct[hh * 170 + c];
    }
}

// ===========================================================================
// Branch1 layer2: a2[b,o,t] = sum_h W2[o,h] * s1u8[b,h,t]  (h ascending)
// 256 threads, tile 20o x 128t, BK=32 double-buffered.
// A = W2 dup pairs (broadcast), B = spikes natural pairs (1 LDS.64).
// Thread: tx=tid&63 -> 2 t (1 pair), ty=tid>>6 -> 5 o.  acc[5].
// ===========================================================================
__global__ __launch_bounds__(256) void k_gemm_b1l2(const float* __restrict__ W2) {
    __shared__ ull   Wsd[2][32 * 21];
    __shared__ float Ssf[2][32 * 132];

    const int b  = blockIdx.y;
    const int t0 = blockIdx.x * 128;
    const int tid = threadIdx.x;
    const int tx = tid & 63, ty = tid >> 6;
    const unsigned char* Sb = g_s1u8 + (size_t)b * HID * TT + t0;

    ull acc[5];
#pragma unroll
    for (int q = 0; q < 5; q++) acc[q] = 0ULL;

    // fill maps
    // W: idx<640: o=idx>>5, k=idx&31 (3 its, last masked)
    // S: idx<1024: k=idx>>5, t4=idx&31 (4 its)
    float vwf[3];  uchar4 vu[4];

    // ---- prologue slab 0 ----
#pragma unroll
    for (int it = 0; it < 3; it++) {
        int idx = tid + 256 * it;
        if (idx < 640) vwf[it] = W2[(idx >> 5) * HID + (idx & 31)];
    }
#pragma unroll
    for (int it = 0; it < 4; it++) {
        int idx = tid + 256 * it;
        vu[it] = *(const uchar4*)(Sb + (size_t)(idx >> 5) * TT + (idx & 31) * 4);
    }
    {
#pragma unroll
        for (int it = 0; it < 3; it++) {
            int idx = tid + 256 * it;
            if (idx < 640) Wsd[0][(idx & 31) * 21 + (idx >> 5)] = dup2(vwf[it]);
        }
#pragma unroll
        for (int it = 0; it < 4; it++) {
            int idx = tid + 256 * it;
            *(float4*)&Ssf[0][(idx >> 5) * 132 + (idx & 31) * 4] =
                make_float4((float)vu[it].x, (float)vu[it].y,
                            (float)vu[it].z, (float)vu[it].w);
        }
    }
    __syncthreads();

    for (int s = 0; s < HID / 32; s++) {
        const int buf = s & 1;
        const bool more = (s + 1 < HID / 32);
        if (more) {
            int k0 = (s + 1) * 32;
#pragma unroll
            for (int it = 0; it < 3; it++) {
                int idx = tid + 256 * it;
                if (idx < 640) vwf[it] = W2[(idx >> 5) * HID + k0 + (idx & 31)];
            }
#pragma unroll
            for (int it = 0; it < 4; it++) {
                int idx = tid + 256 * it;
                vu[it] = *(const uchar4*)(Sb + (size_t)(k0 + (idx >> 5)) * TT
                                             + (idx & 31) * 4);
            }
        }
#pragma unroll
        for (int k = 0; k < 32; k++) {
            const ull* Ar = &Wsd[buf][k * 21 + ty * 5];
            ull a0 = Ar[0], a1 = Ar[1], a2 = Ar[2], a3 = Ar[3], a4 = Ar[4];
            ull bv = *((const ull*)&Ssf[buf][k * 132] + tx);
            ffma2(acc[0], a0, bv);
            ffma2(acc[1], a1, bv);
            ffma2(acc[2], a2, bv);
            ffma2(acc[3], a3, bv);
            ffma2(acc[4], a4, bv);
        }
        if (more) {
#pragma unroll
            for (int it = 0; it < 3; it++) {
                int idx = tid + 256 * it;
                if (idx < 640) Wsd[buf^1][(idx & 31) * 21 + (idx >> 5)] = dup2(vwf[it]);
            }
#pragma unroll
            for (int it = 0; it < 4; it++) {
                int idx = tid + 256 * it;
                *(float4*)&Ssf[buf^1][(idx >> 5) * 132 + (idx & 31) * 4] =
                    make_float4((float)vu[it].x, (float)vu[it].y,
                                (float)vu[it].z, (float)vu[it].w);
            }
            __syncthreads();
        }
    }

    // epilogue: pairs over t -> direct gmem store
#pragma unroll
    for (int q = 0; q < 5; q++) {
        int o = ty * 5 + q;   // 0..19 exactly
        *(ull*)(g_a2 + ((size_t)b * NOUT + o) * TT + t0 + tx * 2) = acc[q];
    }
}

// ---------------------------------------------------------------------------
// Warp-per-row output scans
// ---------------------------------------------------------------------------
__device__ __forceinline__ void scan_rows(const float* __restrict__ in,
                                          float* __restrict__ out,
                                          int len, int out_off) {
    __shared__ float4 buf[8][32];
    const int w = threadIdx.x >> 5, lane = threadIdx.x & 31;
    const int row = blockIdx.x * 8 + w;
    const float* ip = in + (size_t)row * len;
    float* op = out + (size_t)row * OUTT + out_off;
    const int nch = (len + 127) / 128;

    float y = 0.0f;
    int idx = lane * 4;
    float4 v = make_float4(0.f, 0.f, 0.f, 0.f);
    if (idx < len) v = *(const float4*)(ip + idx);

    for (int ch = 0; ch < nch; ch++) {
        buf[w][lane] = v;
        __syncwarp();
        int nidx = (ch + 1) * 128 + lane * 4;
        if (nidx < len) v = *(const float4*)(ip + nidx);
        if (lane == 0) {
            int n4 = (len - ch * 128) >> 2; if (n4 > 32) n4 = 32;
            for (int i = 0; i < n4; i++) {
                float4 u = buf[w][i]; float4 s;
                y = fmaf(ALPHA_F, y, u.x); s.x = (y >= THETA_F) ? 1.0f : 0.0f;
                y = fmaf(ALPHA_F, y, u.y); s.y = (y >= THETA_F) ? 1.0f : 0.0f;
                y = fmaf(ALPHA_F, y, u.z); s.z = (y >= THETA_F) ? 1.0f : 0.0f;
                y = fmaf(ALPHA_F, y, u.w); s.w = (y >= THETA_F) ? 1.0f : 0.0f;
                buf[w][i] = s;
            }
        }
        __syncwarp();
        int oi = ch * 128 + lane * 4;
        if (oi < len) *(float4*)(op + oi) = buf[w][lane];
        __syncwarp();
    }
}

__global__ __launch_bounds__(256) void k_scan_a2(float* __restrict__ out) {
    scan_rows(g_a2, out, TT, 0);
}
__global__ __launch_bounds__(256) void k_scan_l2(float* __restrict__ out) {
    scan_rows(g_l2, out, CIN, TT);
}

// ---------------------------------------------------------------------------
// Branch2 layer2: l2[b,o,c] = sum_h Wl2[o,h] * l1[b,c,h]  (h ascending)
// ---------------------------------------------------------------------------
__global__ __launch_bounds__(160) void k_gemm_b2l2(const float* __restrict__ Wl2) {
    __shared__ float Ws[4 * HID];
    const int og = blockIdx.x;
    const int b  = blockIdx.y;
    const int tid = threadIdx.x;

    for (int idx = tid; idx < 4 * HID; idx += 160)
        Ws[idx] = Wl2[(og * 4 + (idx >> 9)) * HID + (idx & (HID - 1))];
    __syncthreads();

    const int c = tid;
    if (c >= CIN) return;
    const float* Lb = g_l1 + ((size_t)b * CIN + c) * HID;
    float acc[4] = {0.f, 0.f, 0.f, 0.f};

#pragma unroll 4
    for (int h = 0; h < HID; h += 4) {
        float4 xv = *(const float4*)(Lb + h);
#pragma unroll
        for (int o = 0; o < 4; o++) {
            const float4 w = *(const float4*)&Ws[o * HID + h];
            acc[o] = fmaf(w.x, xv.x, acc[o]);
            acc[o] = fmaf(w.y, xv.y, acc[o]);
            acc[o] = fmaf(w.z, xv.z, acc[o]);
            acc[o] = fmaf(w.w, xv.w, acc[o]);
        }
    }
#pragma unroll
    for (int o = 0; o < 4; o++)
        g_l2[((size_t)b * NOUT + og * 4 + o) * CIN + c] = acc[o];
}

// ---------------------------------------------------------------------------
// Launch
// ---------------------------------------------------------------------------
extern "C" void kernel_launch(void* const* d_in, const int* in_sizes, int n_in,
                              void* d_out, int out_size) {
    (void)in_sizes; (void)n_in; (void)out_size;
    const float* X    = (const float*)d_in[0];
    const float* W1   = (const float*)d_in[1];
    const float* W2   = (const float*)d_in[2];
    const float* Wl1  = (const float*)d_in[3];
    const float* Wl2  = (const float*)d_in[4];
    const int*   perm = (const int*)d_in[5];
    float* out = (float*)d_out;

    cudaFuncSetAttribute(k_b1l1_psp, cudaFuncAttributeMaxDynamicSharedMemorySize, B1_SMEM);
    cudaFuncSetAttribute(k_b2l1_psp, cudaFuncAttributeMaxDynamicSharedMemorySize, B2_SMEM);

    // Branch 1
    k_b1l1_psp<<<dim3(HID / 128, BB), 512, B1_SMEM>>>(X, W1);
    k_gemm_b1l2<<<dim3(TT / 128, BB), 256>>>(W2);
    k_scan_a2<<<BB * NOUT / 8, 256>>>(out);

    // Branch 2
    k_b2l1_psp<<<dim3(HID / 128, BB), 512, B2_SMEM>>>(X, Wl1, perm);
    k_gemm_b2l2<<<dim3(5, BB), 160>>>(Wl2);
    k_scan_l2<<<BB * NOUT / 8, 256>>>(out);
}

// round 9
// speedup vs baseline: 1.5338x; 1.0271x over previous
#include <cuda_runtime.h>
#include <cstdint>

// SLAYER constants
#define ALPHA_F 0.90483741803595952f
#define THETA_F 10.0f

// Problem dims
#define BB   32
#define CIN  156
#define TT   2048
#define HID  512
#define NOUT 20
#define OUTT (TT + CIN)   // 2204

typedef unsigned long long ull;

// ---------------------------------------------------------------------------
// Scratch
// ---------------------------------------------------------------------------
__device__ unsigned char g_s1u8[(size_t)BB * HID * TT];  // branch1 layer1 spikes (u8)
__device__ float         g_a2[(size_t)BB * NOUT * TT];   // branch1 layer2 pre-acts
__device__ float         g_l1[(size_t)BB * CIN * HID];   // branch2 spikes, [b][c][h]
__device__ float         g_l2[(size_t)BB * NOUT * CIN];  // branch2 layer2 pre-acts

// packed fp32x2 FMA: two independent rn-rounded fp32 FMAs (bitwise == scalar fmaf)
__device__ __forceinline__ void ffma2(ull& d, ull a, ull b) {
    asm("fma.rn.f32x2 %0, %1, %2, %0;" : "+l"(d) : "l"(a), "l"(b));
}
__device__ __forceinline__ ull dup2(float v) {
    float2 f = make_float2(v, v);
    return *(ull*)&f;
}

// ===========================================================================
// FUSED branch1 layer1 + psp + spike.  (unchanged from round 8 — FMA-bound)
// ===========================================================================
#define B1_SMEM 135424

__global__ __launch_bounds__(512) void k_b1l1_psp(const float* __restrict__ X,
                                                  const float* __restrict__ W1) {
    extern __shared__ char sm[];
    ull*   Asd = (ull*)sm;                         // [2][16*133]
    float* Bsf = (float*)(sm + 34048);             // [2][16*132]
    float* Ct  = (float*)(sm + 50944);             // [128][132]
    unsigned char* Cu8 = (unsigned char*)(sm + 118528);

    const int b  = blockIdx.y;
    const int h0 = blockIdx.x * 128;
    const int tid = threadIdx.x;
    const int tx = tid & 31, ty = tid >> 5;
    const int ha = tid >> 2, cq = tid & 3;         // A-fill map
    const int kb = tid >> 5, t4 = tid & 31;        // B-fill map
    const float* Xb = X + (size_t)b * CIN * TT;
    const float* Wr = W1 + (size_t)(h0 + ha) * CIN;

    float ycar = 0.0f;                             // psp carry (threads 0..127)

    for (int t0 = 0; t0 < TT; t0 += 128) {
        ull acc[8][2];
#pragma unroll
        for (int i = 0; i < 8; i++) { acc[i][0] = 0ULL; acc[i][1] = 0ULL; }

        float4 va, vb;
        {
            int c = cq * 4;
            va = (c < CIN) ? *(const float4*)(Wr + c) : make_float4(0.f,0.f,0.f,0.f);
            vb = (kb < CIN) ? *(const float4*)(Xb + (size_t)kb * TT + t0 + t4 * 4)
                            : make_float4(0.f,0.f,0.f,0.f);
        }
        {
            ull* Ad = Asd;  float* Bd = Bsf;
            Ad[(cq*4+0)*133 + ha] = dup2(va.x);
            Ad[(cq*4+1)*133 + ha] = dup2(va.y);
            Ad[(cq*4+2)*133 + ha] = dup2(va.z);
            Ad[(cq*4+3)*133 + ha] = dup2(va.w);
            *(float4*)(Bd + kb*132 + t4*4) = vb;
        }
        __syncthreads();

        for (int s = 0; s < 10; s++) {
            const int buf = s & 1;
            const bool more = (s + 1 < 10);
            if (more) {
                int k0 = (s + 1) * 16;
                int c  = k0 + cq * 4;
                va = (c < CIN) ? *(const float4*)(Wr + c) : make_float4(0.f,0.f,0.f,0.f);
                int ck = k0 + kb;
                vb = (ck < CIN) ? *(const float4*)(Xb + (size_t)ck * TT + t0 + t4 * 4)
                                : make_float4(0.f,0.f,0.f,0.f);
            }
            const ull*   Ab = Asd + buf * (16*133);
            const float* Bb = Bsf + buf * (16*132);
#pragma unroll
            for (int k = 0; k < 16; k++) {
                const ull* Ar = Ab + k * 133 + ty * 8;
                ull a0 = Ar[0], a1 = Ar[1], a2 = Ar[2], a3 = Ar[3];
                ull a4 = Ar[4], a5 = Ar[5], a6 = Ar[6], a7 = Ar[7];
                ulonglong2 bb = *((const ulonglong2*)(Bb + k * 132) + tx);
                ffma2(acc[0][0], a0, bb.x); ffma2(acc[0][1], a0, bb.y);
                ffma2(acc[1][0], a1, bb.x); ffma2(acc[1][1], a1, bb.y);
                ffma2(acc[2][0], a2, bb.x); ffma2(acc[2][1], a2, bb.y);
                ffma2(acc[3][0], a3, bb.x); ffma2(acc[3][1], a3, bb.y);
                ffma2(acc[4][0], a4, bb.x); ffma2(acc[4][1], a4, bb.y);
                ffma2(acc[5][0], a5, bb.x); ffma2(acc[5][1], a5, bb.y);
                ffma2(acc[6][0], a6, bb.x); ffma2(acc[6][1], a6, bb.y);
                ffma2(acc[7][0], a7, bb.x); ffma2(acc[7][1], a7, bb.y);
            }
            if (more) {
                ull* Ad = Asd + (buf ^ 1) * (16*133);
                float* Bd = Bsf + (buf ^ 1) * (16*132);
                Ad[(cq*4+0)*133 + ha] = dup2(va.x);
                Ad[(cq*4+1)*133 + ha] = dup2(va.y);
                Ad[(cq*4+2)*133 + ha] = dup2(va.z);
                Ad[(cq*4+3)*133 + ha] = dup2(va.w);
                *(float4*)(Bd + kb*132 + t4*4) = vb;
                __syncthreads();
            }
        }

        // epilogue: acc -> Ct[h][t]
#pragma unroll
        for (int i = 0; i < 8; i++) {
#pragma unroll
            for (int j = 0; j < 2; j++) {
                float2 f = *(float2*)&acc[i][j];
                *(float2*)(Ct + (ty*8 + i)*132 + tx*4 + 2*j) = f;
            }
        }
        __syncthreads();

        // fused psp scan + spike
        if (tid < 128) {
            float y = ycar;
            const float* row = Ct + tid * 132;
            unsigned* orow = (unsigned*)(Cu8 + tid * 132);
#pragma unroll 4
            for (int q = 0; q < 32; q++) {
                float4 v = *(const float4*)(row + q * 4);
                unsigned pk;
                y = fmaf(ALPHA_F, y, v.x); pk  = (y >= THETA_F) ? 1u : 0u;
                y = fmaf(ALPHA_F, y, v.y); pk |= (y >= THETA_F) ? (1u<<8) : 0u;
                y = fmaf(ALPHA_F, y, v.z); pk |= (y >= THETA_F) ? (1u<<16) : 0u;
                y = fmaf(ALPHA_F, y, v.w); pk |= (y >= THETA_F) ? (1u<<24) : 0u;
                orow[q] = pk;
            }
            ycar = y;
        }
        __syncthreads();

        // coalesced u8 copy-out
        unsigned char* dstb = g_s1u8 + ((size_t)b * HID + h0) * TT + t0;
#pragma unroll
        for (int it = 0; it < 8; it++) {
            int idx = tid + 512 * it;
            int row = idx >> 5, q = idx & 31;
            unsigned v = *(const unsigned*)(Cu8 + row * 132 + q * 4);
            *(unsigned*)(dstb + (size_t)row * TT + q * 4) = v;
        }
        __syncthreads();
    }
}

// ===========================================================================
// FUSED branch2 layer1 + psp + spike  (REBUILT: 256 thr, 8h x 10c, strided
// c-pairs -> conflict-free B LDS.64, FMA-bound).
//   l1a[b,h,c] = sum_t Wl1[h,t]*X[b,perm[c],t] (t ascending 0..2047)
//   scan over c; spikes (f32) -> g_l1[b][c][h].
// Thread: tx=tid&15 -> c-pairs {tx+16q}, q=0..4 ; ty=tid>>4 -> 8 h.
// smem: Asd ull[2][16*130] @0 (33280) | Bsd ull[2][16*81] @33280 (20736)
//       Ct f32[128][162] @54016 (82944) | prow @136960  total 137600
// ===========================================================================
#define B2_SMEM 137600

__global__ __launch_bounds__(256) void k_b2l1_psp(const float* __restrict__ X,
                                                  const float* __restrict__ Wl1,
                                                  const int* __restrict__ perm) {
    extern __shared__ char sm[];
    ull*   Asd = (ull*)sm;                        // [2][16*130]
    ull*   Bsd = (ull*)(sm + 33280);              // [2][16*81]
    float* Ct  = (float*)(sm + 54016);            // [128][162]
    int*   prow = (int*)(sm + 136960);

    const int b  = blockIdx.y;
    const int h0 = blockIdx.x * 128;
    const int tid = threadIdx.x;
    const int tx = tid & 15, ty = tid >> 4;
    const int ha = tid >> 1, kqa = tid & 1;       // A fill: h=ha, k = kqa*8..+7
    const float* Xb = X + (size_t)b * CIN * TT;
    const float* Wr = Wl1 + (size_t)(h0 + ha) * TT + kqa * 8;

    if (tid < 160) prow[tid] = (tid < CIN) ? perm[tid] : 0;
    __syncthreads();

    ull acc[8][5];
#pragma unroll
    for (int i = 0; i < 8; i++)
#pragma unroll
        for (int q = 0; q < 5; q++) acc[i][q] = 0ULL;

    // ---- fill helpers (inline) ----
    // A: 128h x 16k floats; thread loads 8 floats (2 float4) from its h-row.
    // B: 160c x 4 kq items; idx = tid + 256*it, it=0..2 (last partially masked).
    float4 va0, va1, vb[3];

    // prologue: slab 0 loads
    va0 = *(const float4*)(Wr);
    va1 = *(const float4*)(Wr + 4);
#pragma unroll
    for (int it = 0; it < 3; it++) {
        int idx = tid + 256 * it;
        if (idx < 640) {
            int c = idx >> 2, kq = idx & 3;
            vb[it] = *(const float4*)(Xb + (size_t)prow[c] * TT + kq * 4);
        }
    }
    // prologue: slab 0 stores
    {
        ull* Ad = Asd;
        int kb = kqa * 8;
        Ad[(kb+0)*130 + ha] = dup2(va0.x);
        Ad[(kb+1)*130 + ha] = dup2(va0.y);
        Ad[(kb+2)*130 + ha] = dup2(va0.z);
        Ad[(kb+3)*130 + ha] = dup2(va0.w);
        Ad[(kb+4)*130 + ha] = dup2(va1.x);
        Ad[(kb+5)*130 + ha] = dup2(va1.y);
        Ad[(kb+6)*130 + ha] = dup2(va1.z);
        Ad[(kb+7)*130 + ha] = dup2(va1.w);
#pragma unroll
        for (int it = 0; it < 3; it++) {
            int idx = tid + 256 * it;
            if (idx < 640) {
                int c = idx >> 2, kq = idx & 3;
                int p = c >> 1, hf = c & 1;
                ((float*)(Bsd + (size_t)(kq*4+0)*81 + p))[hf] = vb[it].x;
                ((float*)(Bsd + (size_t)(kq*4+1)*81 + p))[hf] = vb[it].y;
                ((float*)(Bsd + (size_t)(kq*4+2)*81 + p))[hf] = vb[it].z;
                ((float*)(Bsd + (size_t)(kq*4+3)*81 + p))[hf] = vb[it].w;
            }
        }
    }
    __syncthreads();

    for (int s = 0; s < TT / 16; s++) {
        const int buf = s & 1;
        const bool more = (s + 1 < TT / 16);
        if (more) {
            int k0 = (s + 1) * 16;
            va0 = *(const float4*)(Wr + k0);
            va1 = *(const float4*)(Wr + k0 + 4);
#pragma unroll
            for (int it = 0; it < 3; it++) {
                int idx = tid + 256 * it;
                if (idx < 640) {
                    int c = idx >> 2, kq = idx & 3;
                    vb[it] = *(const float4*)(Xb + (size_t)prow[c] * TT + k0 + kq * 4);
                }
            }
        }
        const ull* Ab = Asd + buf * (16*130);
        const ull* Bb = Bsd + buf * (16*81);
#pragma unroll
        for (int k = 0; k < 16; k++) {
            const ull* Ar = Ab + k * 130 + ty * 8;
            ull a0 = Ar[0], a1 = Ar[1], a2 = Ar[2], a3 = Ar[3];
            ull a4 = Ar[4], a5 = Ar[5], a6 = Ar[6], a7 = Ar[7];
            const ull* Br = Bb + k * 81;
            ull b0 = Br[tx], b1 = Br[tx+16], b2 = Br[tx+32],
                b3 = Br[tx+48], b4 = Br[tx+64];
            ffma2(acc[0][0], a0, b0); ffma2(acc[1][0], a1, b0);
            ffma2(acc[2][0], a2, b0); ffma2(acc[3][0], a3, b0);
            ffma2(acc[4][0], a4, b0); ffma2(acc[5][0], a5, b0);
            ffma2(acc[6][0], a6, b0); ffma2(acc[7][0], a7, b0);
            ffma2(acc[0][1], a0, b1); ffma2(acc[1][1], a1, b1);
            ffma2(acc[2][1], a2, b1); ffma2(acc[3][1], a3, b1);
            ffma2(acc[4][1], a4, b1); ffma2(acc[5][1], a5, b1);
            ffma2(acc[6][1], a6, b1); ffma2(acc[7][1], a7, b1);
            ffma2(acc[0][2], a0, b2); ffma2(acc[1][2], a1, b2);
            ffma2(acc[2][2], a2, b2); ffma2(acc[3][2], a3, b2);
            ffma2(acc[4][2], a4, b2); ffma2(acc[5][2], a5, b2);
            ffma2(acc[6][2], a6, b2); ffma2(acc[7][2], a7, b2);
            ffma2(acc[0][3], a0, b3); ffma2(acc[1][3], a1, b3);
            ffma2(acc[2][3], a2, b3); ffma2(acc[3][3], a3, b3);
            ffma2(acc[4][3], a4, b3); ffma2(acc[5][3], a5, b3);
            ffma2(acc[6][3], a6, b3); ffma2(acc[7][3], a7, b3);
            ffma2(acc[0][4], a0, b4); ffma2(acc[1][4], a1, b4);
            ffma2(acc[2][4], a2, b4); ffma2(acc[3][4], a3, b4);
            ffma2(acc[4][4], a4, b4); ffma2(acc[5][4], a5, b4);
            ffma2(acc[6][4], a6, b4); ffma2(acc[7][4], a7, b4);
        }
        if (more) {
            ull* Ad = Asd + (buf ^ 1) * (16*130);
            ull* Bd = Bsd + (buf ^ 1) * (16*81);
            int kb = kqa * 8;
            Ad[(kb+0)*130 + ha] = dup2(va0.x);
            Ad[(kb+1)*130 + ha] = dup2(va0.y);
            Ad[(kb+2)*130 + ha] = dup2(va0.z);
            Ad[(kb+3)*130 + ha] = dup2(va0.w);
            Ad[(kb+4)*130 + ha] = dup2(va1.x);
            Ad[(kb+5)*130 + ha] = dup2(va1.y);
            Ad[(kb+6)*130 + ha] = dup2(va1.z);
            Ad[(kb+7)*130 + ha] = dup2(va1.w);
#pragma unroll
            for (int it = 0; it < 3; it++) {
                int idx = tid + 256 * it;
                if (idx < 640) {
                    int c = idx >> 2, kq = idx & 3;
                    int p = c >> 1, hf = c & 1;
                    ((float*)(Bd + (size_t)(kq*4+0)*81 + p))[hf] = vb[it].x;
                    ((float*)(Bd + (size_t)(kq*4+1)*81 + p))[hf] = vb[it].y;
                    ((float*)(Bd + (size_t)(kq*4+2)*81 + p))[hf] = vb[it].z;
                    ((float*)(Bd + (size_t)(kq*4+3)*81 + p))[hf] = vb[it].w;
                }
            }
            __syncthreads();
        }
    }

    // ---- epilogue: acc (pairs over c at p = tx+16q) -> Ct[h][c] ----
    __syncthreads();
#pragma unroll
    for (int i = 0; i < 8; i++)
#pragma unroll
        for (int q = 0; q < 5; q++) {
            float2 f = *(float2*)&acc[i][q];
            int p = tx + 16 * q;
            *(float2*)(Ct + (ty*8 + i)*162 + 2*p) = f;
        }
    __syncthreads();

    // ---- fused psp scan over c + spike (in-place float) ----
    if (tid < 128) {
        float y = 0.0f;
        float* row = Ct + tid * 162;
#pragma unroll 4
        for (int c = 0; c < CIN; c++) {
            y = fmaf(ALPHA_F, y, row[c]);
            row[c] = (y >= THETA_F) ? 1.0f : 0.0f;
        }
    }
    __syncthreads();

    // ---- coalesced store to g_l1[b][c][h0..h0+127] ----
    float* dstb = g_l1 + (size_t)b * CIN * HID + h0;
    for (int idx = tid; idx < CIN * 128; idx += 256) {
        int c = idx >> 7, hh = idx & 127;
        dstb[(size_t)c * HID + hh] = Ct[hh * 162 + c];
    }
}

// ===========================================================================
// Branch1 layer2: a2[b,o,t] = sum_h W2[o,h] * s1u8[b,h,t]  (unchanged)
// ===========================================================================
__global__ __launch_bounds__(256) void k_gemm_b1l2(const float* __restrict__ W2) {
    __shared__ ull   Wsd[2][32 * 21];
    __shared__ float Ssf[2][32 * 132];

    const int b  = blockIdx.y;
    const int t0 = blockIdx.x * 128;
    const int tid = threadIdx.x;
    const int tx = tid & 63, ty = tid >> 6;
    const unsigned char* Sb = g_s1u8 + (size_t)b * HID * TT + t0;

    ull acc[5];
#pragma unroll
    for (int q = 0; q < 5; q++) acc[q] = 0ULL;

    float vwf[3];  uchar4 vu[4];

#pragma unroll
    for (int it = 0; it < 3; it++) {
        int idx = tid + 256 * it;
        if (idx < 640) vwf[it] = W2[(idx >> 5) * HID + (idx & 31)];
    }
#pragma unroll
    for (int it = 0; it < 4; it++) {
        int idx = tid + 256 * it;
        vu[it] = *(const uchar4*)(Sb + (size_t)(idx >> 5) * TT + (idx & 31) * 4);
    }
    {
#pragma unroll
        for (int it = 0; it < 3; it++) {
            int idx = tid + 256 * it;
            if (idx < 640) Wsd[0][(idx & 31) * 21 + (idx >> 5)] = dup2(vwf[it]);
        }
#pragma unroll
        for (int it = 0; it < 4; it++) {
            int idx = tid + 256 * it;
            *(float4*)&Ssf[0][(idx >> 5) * 132 + (idx & 31) * 4] =
                make_float4((float)vu[it].x, (float)vu[it].y,
                            (float)vu[it].z, (float)vu[it].w);
        }
    }
    __syncthreads();

    for (int s = 0; s < HID / 32; s++) {
        const int buf = s & 1;
        const bool more = (s + 1 < HID / 32);
        if (more) {
            int k0 = (s + 1) * 32;
#pragma unroll
            for (int it = 0; it < 3; it++) {
                int idx = tid + 256 * it;
                if (idx < 640) vwf[it] = W2[(idx >> 5) * HID + k0 + (idx & 31)];
            }
#pragma unroll
            for (int it = 0; it < 4; it++) {
                int idx = tid + 256 * it;
                vu[it] = *(const uchar4*)(Sb + (size_t)(k0 + (idx >> 5)) * TT
                                             + (idx & 31) * 4);
            }
        }
#pragma unroll
        for (int k = 0; k < 32; k++) {
            const ull* Ar = &Wsd[buf][k * 21 + ty * 5];
            ull a0 = Ar[0], a1 = Ar[1], a2 = Ar[2], a3 = Ar[3], a4 = Ar[4];
            ull bv = *((const ull*)&Ssf[buf][k * 132] + tx);
            ffma2(acc[0], a0, bv);
            ffma2(acc[1], a1, bv);
            ffma2(acc[2], a2, bv);
            ffma2(acc[3], a3, bv);
            ffma2(acc[4], a4, bv);
        }
        if (more) {
#pragma unroll
            for (int it = 0; it < 3; it++) {
                int idx = tid + 256 * it;
                if (idx < 640) Wsd[buf^1][(idx & 31) * 21 + (idx >> 5)] = dup2(vwf[it]);
            }
#pragma unroll
            for (int it = 0; it < 4; it++) {
                int idx = tid + 256 * it;
                *(float4*)&Ssf[buf^1][(idx >> 5) * 132 + (idx & 31) * 4] =
                    make_float4((float)vu[it].x, (float)vu[it].y,
                                (float)vu[it].z, (float)vu[it].w);
            }
            __syncthreads();
        }
    }

#pragma unroll
    for (int q = 0; q < 5; q++) {
        int o = ty * 5 + q;
        *(ull*)(g_a2 + ((size_t)b * NOUT + o) * TT + t0 + tx * 2) = acc[q];
    }
}

// ---------------------------------------------------------------------------
// Warp-per-row output scans (unchanged)
// ---------------------------------------------------------------------------
__device__ __forceinline__ void scan_rows(const float* __restrict__ in,
                                          float* __restrict__ out,
                                          int len, int out_off) {
    __shared__ float4 buf[8][32];
    const int w = threadIdx.x >> 5, lane = threadIdx.x & 31;
    const int row = blockIdx.x * 8 + w;
    const float* ip = in + (size_t)row * len;
    float* op = out + (size_t)row * OUTT + out_off;
    const int nch = (len + 127) / 128;

    float y = 0.0f;
    int idx = lane * 4;
    float4 v = make_float4(0.f, 0.f, 0.f, 0.f);
    if (idx < len) v = *(const float4*)(ip + idx);

    for (int ch = 0; ch < nch; ch++) {
        buf[w][lane] = v;
        __syncwarp();
        int nidx = (ch + 1) * 128 + lane * 4;
        if (nidx < len) v = *(const float4*)(ip + nidx);
        if (lane == 0) {
            int n4 = (len - ch * 128) >> 2; if (n4 > 32) n4 = 32;
            for (int i = 0; i < n4; i++) {
                float4 u = buf[w][i]; float4 s;
                y = fmaf(ALPHA_F, y, u.x); s.x = (y >= THETA_F) ? 1.0f : 0.0f;
                y = fmaf(ALPHA_F, y, u.y); s.y = (y >= THETA_F) ? 1.0f : 0.0f;
                y = fmaf(ALPHA_F, y, u.z); s.z = (y >= THETA_F) ? 1.0f : 0.0f;
                y = fmaf(ALPHA_F, y, u.w); s.w = (y >= THETA_F) ? 1.0f : 0.0f;
                buf[w][i] = s;
            }
        }
        __syncwarp();
        int oi = ch * 128 + lane * 4;
        if (oi < len) *(float4*)(op + oi) = buf[w][lane];
        __syncwarp();
    }
}

__global__ __launch_bounds__(256) void k_scan_a2(float* __restrict__ out) {
    scan_rows(g_a2, out, TT, 0);
}
__global__ __launch_bounds__(256) void k_scan_l2(float* __restrict__ out) {
    scan_rows(g_l2, out, CIN, TT);
}

// ---------------------------------------------------------------------------
// Branch2 layer2: l2[b,o,c] = sum_h Wl2[o,h] * l1[b,c,h]  (unchanged)
// ---------------------------------------------------------------------------
__global__ __launch_bounds__(160) void k_gemm_b2l2(const float* __restrict__ Wl2) {
    __shared__ float Ws[4 * HID];
    const int og = blockIdx.x;
    const int b  = blockIdx.y;
    const int tid = threadIdx.x;

    for (int idx = tid; idx < 4 * HID; idx += 160)
        Ws[idx] = Wl2[(og * 4 + (idx >> 9)) * HID + (idx & (HID - 1))];
    __syncthreads();

    const int c = tid;
    if (c >= CIN) return;
    const float* Lb = g_l1 + ((size_t)b * CIN + c) * HID;
    float acc[4] = {0.f, 0.f, 0.f, 0.f};

#pragma unroll 4
    for (int h = 0; h < HID; h += 4) {
        float4 xv = *(const float4*)(Lb + h);
#pragma unroll
        for (int o = 0; o < 4; o++) {
            const float4 w = *(const float4*)&Ws[o * HID + h];
            acc[o] = fmaf(w.x, xv.x, acc[o]);
            acc[o] = fmaf(w.y, xv.y, acc[o]);
            acc[o] = fmaf(w.z, xv.z, acc[o]);
            acc[o] = fmaf(w.w, xv.w, acc[o]);
        }
    }
#pragma unroll
    for (int o = 0; o < 4; o++)
        g_l2[((size_t)b * NOUT + og * 4 + o) * CIN + c] = acc[o];
}

// ---------------------------------------------------------------------------
// Launch
// ---------------------------------------------------------------------------
extern "C" void kernel_launch(void* const* d_in, const int* in_sizes, int n_in,
                              void* d_out, int out_size) {
    (void)in_sizes; (void)n_in; (void)out_size;
    const float* X    = (const float*)d_in[0];
    const float* W1   = (const float*)d_in[1];
    const float* W2   = (const float*)d_in[2];
    const float* Wl1  = (const float*)d_in[3];
    const float* Wl2  = (const float*)d_in[4];
    const int*   perm = (const int*)d_in[5];
    float* out = (float*)d_out;

    cudaFuncSetAttribute(k_b1l1_psp, cudaFuncAttributeMaxDynamicSharedMemorySize, B1_SMEM);
    cudaFuncSetAttribute(k_b2l1_psp, cudaFuncAttributeMaxDynamicSharedMemorySize, B2_SMEM);

    // Branch 1
    k_b1l1_psp<<<dim3(HID / 128, BB), 512, B1_SMEM>>>(X, W1);
    k_gemm_b1l2<<<dim3(TT / 128, BB), 256>>>(W2);
    k_scan_a2<<<BB * NOUT / 8, 256>>>(out);

    // Branch 2
    k_b2l1_psp<<<dim3(HID / 128, BB), 256, B2_SMEM>>>(X, Wl1, perm);
    k_gemm_b2l2<<<dim3(5, BB), 160>>>(Wl2);
    k_scan_l2<<<BB * NOUT / 8, 256>>>(out);
}